// round 9
// baseline (speedup 1.0000x reference)
#include <cuda_runtime.h>

typedef unsigned long long u64;

#define THREADS 640
#define NATOM   128
#define KNB     127
#define NBATCH  64
#define BT      8

// ---- shared memory float offsets (e-strides == 8 mod 32 banks) ----
#define OFF_TY   0        // 128 ints
#define OFF_W0   128      // [e*40 + o]
#define OFF_B0   288
#define OFF_W1   448      // [e*1608 + i*64 + pos], fifths of 10 padded to 12 @ 12*qt
#define E1STR    1608
#define OFF_B1   6880     // [e*72 + pos]
#define OFF_W2   7168     // [e*5608 + i*104 + m], fifths of 20 @ 20*qt
#define E2STR    5608
#define OFF_B2   29600    // [e*136 + m]
#define OFF_CS   30144    // [bb][3][128]
#define OFF_EA   30912    // [bb][k*4+c]
#define OFF_H0   31936    // [bb][slot*27 + r]
#define H0BUF    3429
#define OFF_X    38794    // h1: [bb*6477 + slot*51 + o] / G: [slot*101 + m]
#define H1BUF    6477
#define GSTR     101
#define OFF_UP   51748    // [kq*312 + c*104 + m], 5 chunks
#define OFF_US   53308
#define OFF_SIDX 53620    // 128 ints
#define OFF_CNT  53748
#define OFF_ST   53752
#define SMEM_FLOATS 53760
#define SMEM_BYTES (SMEM_FLOATS * 4)

__device__ __forceinline__ float tanhx(float x) {
    float y; asm("tanh.approx.f32 %0, %1;" : "=f"(y) : "f"(x)); return y;
}
__device__ __forceinline__ u64 pack2(float lo, float hi) {
    u64 r; asm("mov.b64 %0, {%1, %2};" : "=l"(r) : "f"(lo), "f"(hi)); return r;
}
__device__ __forceinline__ float2 unpack2(u64 v) {
    float2 r; asm("mov.b64 {%0, %1}, %2;" : "=f"(r.x), "=f"(r.y) : "l"(v)); return r;
}
__device__ __forceinline__ u64 fma2(u64 a, u64 b, u64 c) {
    u64 r; asm("fma.rn.f32x2 %0, %1, %2, %3;" : "=l"(r) : "l"(a), "l"(b), "l"(c)); return r;
}
#define BARG(id) asm volatile("bar.sync %0, 160;" :: "r"(id) : "memory")

extern __shared__ float sm[];

__global__ void __launch_bounds__(THREADS, 1)
feat_kernel(const float* __restrict__ coords, const int* __restrict__ types,
            const float* __restrict__ W0g, const float* __restrict__ B0g,
            const float* __restrict__ W1g, const float* __restrict__ B1g,
            const float* __restrict__ W2g, const float* __restrict__ B2g,
            float* __restrict__ out)
{
    const int n    = blockIdx.x;
    const int tid  = threadIdx.x;
    const int warp = tid >> 5;
    const int lane = tid & 31;
    const int pw   = warp & 3;    // pair-warp: sorted slots [32pw, 32pw+32)
    const int qt   = warp >> 2;   // output fifth 0..4
    int* smi = (int*)sm;

    const int eb = types[n] * 4;

    // zero weight+bias region (covers all pads)
    for (int i = OFF_W0 + tid; i < OFF_CS; i += THREADS) sm[i] = 0.0f;
    if (tid < 128) smi[OFF_TY + tid] = types[tid];
    __syncthreads();

    // ---- stage weights (transposed) for this atom's 4 sub-types ----
    for (int i = tid; i < 100; i += THREADS) {
        int o = i % 25, e = i / 25;
        sm[OFF_W0 + e * 40 + o] = W0g[(eb + e) * 25 + o];
        sm[OFF_B0 + e * 40 + o] = B0g[(eb + e) * 25 + o];
    }
    for (int idx = tid; idx < 4 * 50 * 25; idx += THREADS) {
        int i = idx % 25, o = (idx / 25) % 50, e = idx / 1250;
        int pos = 12 * (o / 10) + (o % 10);
        sm[OFF_W1 + e * E1STR + i * 64 + pos] = W1g[(eb + e) * 1250 + o * 25 + i];
    }
    for (int idx = tid; idx < 200; idx += THREADS) {
        int o = idx % 50, e = idx / 50;
        int pos = 12 * (o / 10) + (o % 10);
        sm[OFF_B1 + e * 72 + pos] = B1g[(eb + e) * 50 + o];
    }
    for (int idx = tid; idx < 4 * 100 * 50; idx += THREADS) {
        int i = idx % 50, m = (idx / 50) % 100, e = idx / 5000;
        sm[OFF_W2 + e * E2STR + i * 104 + m] = W2g[(eb + e) * 5000 + m * 50 + i];
    }
    for (int idx = tid; idx < 400; idx += THREADS) {
        int m = idx % 100, e = idx / 100;
        sm[OFF_B2 + e * 136 + m] = B2g[(eb + e) * 100 + m];
    }

    // ---- sort neighbors by type (stable) ----
    if (tid < 4) {
        int c = 0;
        for (int j2 = 0; j2 < 128; j2++)
            if (j2 != n && smi[OFF_TY + j2] == tid) c++;
        smi[OFF_CNT + tid] = c;
    }
    __syncthreads();
    if (tid == 0) {
        int s = 0;
        #pragma unroll
        for (int e = 0; e < 4; e++) { smi[OFF_ST + e] = s; s += smi[OFF_CNT + e]; }
        smi[OFF_ST + 4] = s;
    }
    __syncthreads();
    if (tid < 128 && tid != n) {
        int t = smi[OFF_TY + tid];
        int r = 0;
        for (int j2 = 0; j2 < tid; j2++)
            if (j2 != n && smi[OFF_TY + j2] == t) r++;
        smi[OFF_SIDX + smi[OFF_ST + t] + r] = tid;
    }
    __syncthreads();

    const int  slot   = (pw << 5) + lane;         // 0..127; 127 idle
    const bool active = slot < KNB;
    const int  j = active ? smi[OFF_SIDX + slot] : n;
    const int  e = active ? smi[OFF_TY + j] : 0;

    const float* w0e = sm + OFF_W0 + e * 40;
    const float* b0e = sm + OFF_B0 + e * 40;
    const float* w1q = sm + OFF_W1 + e * E1STR + 12 * qt;
    const float* b1q = sm + OFF_B1 + e * 72 + 12 * qt;
    const float* w2q = sm + OFF_W2 + e * E2STR + 20 * qt;
    const float* b2q = sm + OFF_B2 + e * 136 + 20 * qt;
    const int base1 = 10 * qt;     // layer1 fifth: outputs [base1, base1+10)
    const int base2 = 20 * qt;     // layer2 fifth: outputs [base2, base2+20)
    const int base0 = 5 * qt;      // layer0 share: [base0, base0+5)
    float* h0a = sm + OFF_H0 + slot * 27;
    float* h0b = h0a + H0BUF;
    float* h1a = sm + OFF_X + slot * 51;
    float* h1b = h1a + H1BUF;
    const int barid = 1 + pw;

    for (int bi2 = 0; bi2 < BT / 2; bi2++) {
        const int b0i = blockIdx.y * BT + bi2 * 2;
        __syncthreads();   // X / EA / CS reuse guard
        for (int i = tid; i < 2 * 384; i += THREADS) {
            int bb = i / 384, ii = i % 384;
            sm[OFF_CS + bb * 384 + (ii % 3) * 128 + ii / 3] =
                coords[(size_t)(b0i + bb) * 384 + ii];
        }
        __syncthreads();

        if (active) {
            float xa = 0.0f, xb = 0.0f;
            #pragma unroll
            for (int bb = 0; bb < 2; bb++) {
                const float* cs = sm + OFF_CS + bb * 384;
                float rx = cs[n]       - cs[j];
                float ry = cs[128 + n] - cs[128 + j];
                float rz = cs[256 + n] - cs[256 + j];
                float dinv = rsqrtf(rx * rx + ry * ry + rz * rz);
                float di2 = dinv * dinv;
                if (qt == 0) {
                    float* ea = sm + OFF_EA + bb * 512 + slot * 4;
                    ea[0] = rx * di2; ea[1] = ry * di2; ea[2] = rz * di2; ea[3] = 0.0f;
                }
                if (bb == 0) xa = dinv; else xb = dinv;
            }
            // h0 split across 5 co-warps: 5 entries each
            #pragma unroll
            for (int c = 0; c < 5; c++) {
                int r = base0 + c;
                float w = w0e[r], bi = b0e[r];
                h0a[r] = tanhx(fmaf(xa, w, bi));
                h0b[r] = tanhx(fmaf(xb, w, bi));
            }
        }
        BARG(barid);   // h0 ready within pair-group

        // ---- layer1: fifth = 10 outs (12 padded), 2 batches ----
        {
            float h0ra[25], h0rb[25];
            #pragma unroll
            for (int i = 0; i < 25; i++) { h0ra[i] = h0a[i]; h0rb[i] = h0b[i]; }

            u64 acc[2][6];
            #pragma unroll
            for (int t = 0; t < 3; t++) {
                ulonglong2 bb = *(const ulonglong2*)(b1q + t * 4);
                acc[0][2*t] = bb.x; acc[0][2*t+1] = bb.y;
                acc[1][2*t] = bb.x; acc[1][2*t+1] = bb.y;
            }
            #pragma unroll
            for (int i = 0; i < 25; i++) {
                u64 hda = pack2(h0ra[i], h0ra[i]);
                u64 hdb = pack2(h0rb[i], h0rb[i]);
                const float* wp = w1q + i * 64;
                #pragma unroll
                for (int t = 0; t < 3; t++) {
                    ulonglong2 w = *(const ulonglong2*)(wp + t * 4);
                    acc[0][2*t]   = fma2(w.x, hda, acc[0][2*t]);
                    acc[0][2*t+1] = fma2(w.y, hda, acc[0][2*t+1]);
                    acc[1][2*t]   = fma2(w.x, hdb, acc[1][2*t]);
                    acc[1][2*t+1] = fma2(w.y, hdb, acc[1][2*t+1]);
                }
            }
            if (active) {
                #pragma unroll
                for (int q = 0; q < 5; q++) {   // u64 idx 5 is pad
                    float2 va = unpack2(acc[0][q]);
                    float2 vb = unpack2(acc[1][q]);
                    int o0 = base1 + 2 * q, o1 = o0 + 1;
                    int r0 = (o0 < 25) ? o0 : o0 - 25;
                    int r1 = (o1 < 25) ? o1 : o1 - 25;
                    h1a[o0] = tanhx(va.x) + h0ra[r0];
                    h1a[o1] = tanhx(va.y) + h0ra[r1];
                    h1b[o0] = tanhx(vb.x) + h0rb[r0];
                    h1b[o1] = tanhx(vb.y) + h0rb[r1];
                }
            }
        }
        BARG(barid);   // h1 ready within pair-group

        // ---- layer2: fifth = 20 outs, 2 batches; h1 chunk-prefetched ----
        float ga[20], gb[20];
        {
            u64 acc[2][10];
            #pragma unroll
            for (int t = 0; t < 5; t++) {
                ulonglong2 bb = *(const ulonglong2*)(b2q + t * 4);
                acc[0][2*t] = bb.x; acc[0][2*t+1] = bb.y;
                acc[1][2*t] = bb.x; acc[1][2*t+1] = bb.y;
            }
            #pragma unroll
            for (int c = 0; c < 5; c++) {
                float ha[10], hb[10];
                #pragma unroll
                for (int ii = 0; ii < 10; ii++) {
                    ha[ii] = h1a[c * 10 + ii];
                    hb[ii] = h1b[c * 10 + ii];
                }
                #pragma unroll
                for (int ii = 0; ii < 10; ii++) {
                    u64 hda = pack2(ha[ii], ha[ii]);
                    u64 hdb = pack2(hb[ii], hb[ii]);
                    const float* wp = w2q + (c * 10 + ii) * 104;
                    #pragma unroll
                    for (int t = 0; t < 5; t++) {
                        ulonglong2 w = *(const ulonglong2*)(wp + t * 4);
                        acc[0][2*t]   = fma2(w.x, hda, acc[0][2*t]);
                        acc[0][2*t+1] = fma2(w.y, hda, acc[0][2*t+1]);
                        acc[1][2*t]   = fma2(w.x, hdb, acc[1][2*t]);
                        acc[1][2*t+1] = fma2(w.y, hdb, acc[1][2*t+1]);
                    }
                }
            }
            // residual: m = base2 + l -> h1[m mod 50]
            #pragma unroll
            for (int q = 0; q < 10; q++) {
                float2 va = unpack2(acc[0][q]);
                float2 vb = unpack2(acc[1][q]);
                int l0 = 2 * q, l1 = 2 * q + 1;
                int m0 = base2 + l0, m1 = base2 + l1;
                int r0 = (m0 < 50) ? m0 : m0 - 50;
                int r1 = (m1 < 50) ? m1 : m1 - 50;
                ga[l0] = tanhx(va.x) + h1a[r0];
                ga[l1] = tanhx(va.y) + h1a[r1];
                gb[l0] = tanhx(vb.x) + h1b[r0];
                gb[l1] = tanhx(vb.y) + h1b[r1];
            }
        }
        __syncthreads();   // all h1 reads done; X region becomes G

        #pragma unroll
        for (int bb = 0; bb < 2; bb++) {
            if (active) {
                float* grow = sm + OFF_X + slot * GSTR + base2;
                #pragma unroll
                for (int l = 0; l < 20; l++) grow[l] = bb ? gb[l] : ga[l];
            }
            __syncthreads();

            // U[c][m] = sum_k ea[c][k]*G[k][m]; 5 k-chunks of 26 (last 23)
            const int m  = tid & 127;
            const int kq = tid >> 7;
            float u0 = 0.0f, u1 = 0.0f, u2 = 0.0f;
            if (m < 100) {
                const int kb = kq * 26;
                const int ke = (kq == 4) ? KNB : kb + 26;
                const float* gp = sm + OFF_X + m;
                const float* ep = sm + OFF_EA + bb * 512;
                #pragma unroll 4
                for (int kk = kb; kk < ke; kk++) {
                    float4 ea = *(const float4*)(ep + kk * 4);
                    float g = gp[kk * GSTR];
                    u0 = fmaf(ea.x, g, u0);
                    u1 = fmaf(ea.y, g, u1);
                    u2 = fmaf(ea.z, g, u2);
                }
                sm[OFF_UP + kq * 312 + m]       = u0;
                sm[OFF_UP + kq * 312 + 104 + m] = u1;
                sm[OFF_UP + kq * 312 + 208 + m] = u2;
            }
            __syncthreads();
            float us0 = 0.0f, us1 = 0.0f, us2 = 0.0f;
            if (tid < 100) {
                #pragma unroll
                for (int qq = 0; qq < 5; qq++) {
                    us0 += sm[OFF_UP + qq * 312 + tid];
                    us1 += sm[OFF_UP + qq * 312 + 104 + tid];
                    us2 += sm[OFF_UP + qq * 312 + 208 + tid];
                }
                sm[OFF_US + tid]       = us0;
                sm[OFF_US + 104 + tid] = us1;
                sm[OFF_US + 208 + tid] = us2;
            }
            __syncthreads();
            if (tid < 100) {
                float4 r;
                r.x = us0 * sm[OFF_US + 0] + us1 * sm[OFF_US + 104 + 0] + us2 * sm[OFF_US + 208 + 0];
                r.y = us0 * sm[OFF_US + 1] + us1 * sm[OFF_US + 104 + 1] + us2 * sm[OFF_US + 208 + 1];
                r.z = us0 * sm[OFF_US + 2] + us1 * sm[OFF_US + 104 + 2] + us2 * sm[OFF_US + 208 + 2];
                r.w = us0 * sm[OFF_US + 3] + us1 * sm[OFF_US + 104 + 3] + us2 * sm[OFF_US + 208 + 3];
                *(float4*)(out + ((size_t)(b0i + bb) * NATOM + n) * 400 + tid * 4) = r;
            }
            __syncthreads();   // G reads done before next batch's stores
        }
    }
}

extern "C" void kernel_launch(void* const* d_in, const int* in_sizes, int n_in,
                              void* d_out, int out_size)
{
    (void)in_sizes; (void)n_in; (void)out_size;
    const float* coords = (const float*)d_in[0];
    const int*   types  = (const int*)d_in[1];
    const float* W0g = (const float*)d_in[2];
    const float* B0g = (const float*)d_in[3];
    const float* W1g = (const float*)d_in[4];
    const float* B1g = (const float*)d_in[5];
    const float* W2g = (const float*)d_in[6];
    const float* B2g = (const float*)d_in[7];
    float* out = (float*)d_out;

    cudaFuncSetAttribute(feat_kernel, cudaFuncAttributeMaxDynamicSharedMemorySize, SMEM_BYTES);

    dim3 grid(NATOM, NBATCH / BT);   // (128, 8)
    feat_kernel<<<grid, THREADS, SMEM_BYTES>>>(coords, types,
                                               W0g, B0g, W1g, B1g, W2g, B2g, out);
}

// round 10
// speedup vs baseline: 1.1045x; 1.1045x over previous
#include <cuda_runtime.h>

typedef unsigned long long u64;

#define THREADS 512
#define NATOM   128
#define KNB     127
#define NBATCH  64
#define BT      8

// ---- shared memory float offsets (e-strides == 8 mod 32 banks) ----
#define OFF_TY   0
#define OFF_W0   128      // [e*40 + o]
#define OFF_B0   288
#define OFF_W1   448      // [e*1608 + i*64 + pos] quarter tiles 16 @ 16qt (13,13,12,12)
#define E1STR    1608
#define OFF_B1   6880     // [e*72 + pos]
#define OFF_W2   7168     // [e*5608 + i*112 + pos] quarter = 25 contiguous @ 28qt (+3 pad)
#define E2STR    5608
#define OFF_B2   29600    // [e*136 + pos]
#define OFF_CS   30144    // [bb][3][128]   3*384
#define OFF_EA   31296    // [bb][c][128]   3*384
#define OFF_X    32448    // h1: [bb*6477 + slot*51 + i] / G: [slot*101 + m]
#define H1BUF    6477
#define GSTR     101
#define OFF_UP   51879    // [kq*312 + c*104 + m]
#define OFF_US   53127
#define OFF_SIDX 53439
#define OFF_CNT  53567
#define OFF_ST   53571
#define SMEM_FLOATS 53576
#define SMEM_BYTES (SMEM_FLOATS * 4)

__device__ __forceinline__ float tanhx(float x) {
    float y; asm("tanh.approx.f32 %0, %1;" : "=f"(y) : "f"(x)); return y;
}
__device__ __forceinline__ u64 pack2(float lo, float hi) {
    u64 r; asm("mov.b64 %0, {%1, %2};" : "=l"(r) : "f"(lo), "f"(hi)); return r;
}
__device__ __forceinline__ float2 unpack2(u64 v) {
    float2 r; asm("mov.b64 {%0, %1}, %2;" : "=f"(r.x), "=f"(r.y) : "l"(v)); return r;
}
__device__ __forceinline__ u64 fma2(u64 a, u64 b, u64 c) {
    u64 r; asm("fma.rn.f32x2 %0, %1, %2, %3;" : "=l"(r) : "l"(a), "l"(b), "l"(c)); return r;
}
#define BARG(id) asm volatile("bar.sync %0, 128;" :: "r"(id) : "memory")

extern __shared__ float sm[];

template<int NB>
__device__ __forceinline__ void tile_body(
    const float* __restrict__ coords, float* __restrict__ out,
    int n, int tid, int qt, int slot, bool active, int j,
    const float* w0e, const float* b0e,
    const float* w1q, const float* b1q,
    const float* w2q, const float* b2q,
    int tbase1, int sz1, int barid, int b0i)
{
    __syncthreads();   // guard CS/EA/X reuse from previous tile
    for (int i = tid; i < NB * 384; i += THREADS) {
        int bb = i / 384, ii = i % 384;
        sm[OFF_CS + bb * 384 + (ii % 3) * 128 + ii / 3] =
            coords[(size_t)(b0i + bb) * 384 + ii];
    }
    __syncthreads();

    // ---- env: x[b] = 1/d, EA planes (qt==0 writes) ----
    float x[NB];
    #pragma unroll
    for (int bb = 0; bb < NB; bb++) {
        const float* cs = sm + OFF_CS + bb * 384;
        float rx = cs[n]       - cs[j];
        float ry = cs[128 + n] - cs[128 + j];
        float rz = cs[256 + n] - cs[256 + j];
        float dinv = rsqrtf(rx * rx + ry * ry + rz * rz);
        float di2 = dinv * dinv;
        if (qt == 0 && active) {
            float* ea = sm + OFF_EA + bb * 384;
            ea[slot]       = rx * di2;
            ea[128 + slot] = ry * di2;
            ea[256 + slot] = rz * di2;
        }
        x[bb] = dinv;
    }

    // ---- layer1: quarter (16 padded outs), h0 inline, NB batches ----
    {
        u64 acc[NB][8];
        #pragma unroll
        for (int t = 0; t < 4; t++) {
            ulonglong2 bv = *(const ulonglong2*)(b1q + t * 4);
            #pragma unroll
            for (int bb = 0; bb < NB; bb++) { acc[bb][2*t] = bv.x; acc[bb][2*t+1] = bv.y; }
        }
        #pragma unroll 5
        for (int i = 0; i < 25; i++) {
            float w0 = w0e[i], bi0 = b0e[i];
            u64 hd[NB];
            #pragma unroll
            for (int bb = 0; bb < NB; bb++) {
                float h = tanhx(fmaf(x[bb], w0, bi0));
                hd[bb] = pack2(h, h);
            }
            const float* wp = w1q + i * 64;
            #pragma unroll
            for (int t = 0; t < 4; t++) {
                ulonglong2 w = *(const ulonglong2*)(wp + t * 4);
                #pragma unroll
                for (int bb = 0; bb < NB; bb++) {
                    acc[bb][2*t]   = fma2(w.x, hd[bb], acc[bb][2*t]);
                    acc[bb][2*t+1] = fma2(w.y, hd[bb], acc[bb][2*t+1]);
                }
            }
        }
        if (active) {
            #pragma unroll
            for (int q = 0; q < 7; q++) {
                int l0 = 2 * q, l1 = 2 * q + 1;
                #pragma unroll
                for (int bb = 0; bb < NB; bb++) {
                    float2 v = unpack2(acc[bb][q]);
                    float* h1p = sm + OFF_X + bb * H1BUF + slot * 51;
                    if (l0 < sz1) {
                        int o = tbase1 + l0, r = (o < 25) ? o : o - 25;
                        h1p[o] = tanhx(v.x) + tanhx(fmaf(x[bb], w0e[r], b0e[r]));
                    }
                    if (l1 < sz1) {
                        int o = tbase1 + l1, r = (o < 25) ? o : o - 25;
                        h1p[o] = tanhx(v.y) + tanhx(fmaf(x[bb], w0e[r], b0e[r]));
                    }
                }
            }
        }
    }
    BARG(barid);   // h1 complete within pair-group

    // ---- layer2: quarter 25 outs, two register sub-passes ----
    float g[NB][25];
    const int roff = 25 * (qt & 1);
    // sub-pass A: outs l in [0,16)
    {
        u64 acc[NB][8];
        #pragma unroll
        for (int t = 0; t < 4; t++) {
            ulonglong2 bv = *(const ulonglong2*)(b2q + t * 4);
            #pragma unroll
            for (int bb = 0; bb < NB; bb++) { acc[bb][2*t] = bv.x; acc[bb][2*t+1] = bv.y; }
        }
        for (int c = 0; c < 10; c++) {
            float hr[NB][5];
            #pragma unroll
            for (int ii = 0; ii < 5; ii++)
                #pragma unroll
                for (int bb = 0; bb < NB; bb++)
                    hr[bb][ii] = sm[OFF_X + bb * H1BUF + slot * 51 + c * 5 + ii];
            #pragma unroll
            for (int ii = 0; ii < 5; ii++) {
                const float* wp = w2q + (c * 5 + ii) * 112;
                u64 hd[NB];
                #pragma unroll
                for (int bb = 0; bb < NB; bb++) hd[bb] = pack2(hr[bb][ii], hr[bb][ii]);
                #pragma unroll
                for (int t = 0; t < 4; t++) {
                    ulonglong2 w = *(const ulonglong2*)(wp + t * 4);
                    #pragma unroll
                    for (int bb = 0; bb < NB; bb++) {
                        acc[bb][2*t]   = fma2(w.x, hd[bb], acc[bb][2*t]);
                        acc[bb][2*t+1] = fma2(w.y, hd[bb], acc[bb][2*t+1]);
                    }
                }
            }
        }
        #pragma unroll
        for (int q = 0; q < 8; q++) {
            int l0 = 2 * q, l1 = 2 * q + 1;
            #pragma unroll
            for (int bb = 0; bb < NB; bb++) {
                float2 v = unpack2(acc[bb][q]);
                const float* h1p = sm + OFF_X + bb * H1BUF + slot * 51;
                g[bb][l0] = tanhx(v.x) + h1p[roff + l0];
                g[bb][l1] = tanhx(v.y) + h1p[roff + l1];
            }
        }
    }
    // sub-pass B: outs l in [16,25), 12 padded
    {
        u64 acc[NB][6];
        #pragma unroll
        for (int t = 0; t < 3; t++) {
            ulonglong2 bv = *(const ulonglong2*)(b2q + 16 + t * 4);
            #pragma unroll
            for (int bb = 0; bb < NB; bb++) { acc[bb][2*t] = bv.x; acc[bb][2*t+1] = bv.y; }
        }
        for (int c = 0; c < 10; c++) {
            float hr[NB][5];
            #pragma unroll
            for (int ii = 0; ii < 5; ii++)
                #pragma unroll
                for (int bb = 0; bb < NB; bb++)
                    hr[bb][ii] = sm[OFF_X + bb * H1BUF + slot * 51 + c * 5 + ii];
            #pragma unroll
            for (int ii = 0; ii < 5; ii++) {
                const float* wp = w2q + (c * 5 + ii) * 112 + 16;
                u64 hd[NB];
                #pragma unroll
                for (int bb = 0; bb < NB; bb++) hd[bb] = pack2(hr[bb][ii], hr[bb][ii]);
                #pragma unroll
                for (int t = 0; t < 3; t++) {
                    ulonglong2 w = *(const ulonglong2*)(wp + t * 4);
                    #pragma unroll
                    for (int bb = 0; bb < NB; bb++) {
                        acc[bb][2*t]   = fma2(w.x, hd[bb], acc[bb][2*t]);
                        acc[bb][2*t+1] = fma2(w.y, hd[bb], acc[bb][2*t+1]);
                    }
                }
            }
        }
        #pragma unroll
        for (int q = 0; q < 5; q++) {
            int l0 = 16 + 2 * q, l1 = l0 + 1;
            #pragma unroll
            for (int bb = 0; bb < NB; bb++) {
                float2 v = unpack2(acc[bb][q]);
                const float* h1p = sm + OFF_X + bb * H1BUF + slot * 51;
                if (l0 < 25) g[bb][l0] = tanhx(v.x) + h1p[roff + l0];
                if (l1 < 25) g[bb][l1] = tanhx(v.y) + h1p[roff + l1];
            }
        }
    }
    __syncthreads();   // all h1 reads done; X becomes G

    #pragma unroll
    for (int bb = 0; bb < NB; bb++) {
        if (active) {
            float* grow = sm + OFF_X + slot * GSTR + 25 * qt;
            #pragma unroll
            for (int l = 0; l < 25; l++) grow[l] = g[bb][l];
        }
        __syncthreads();

        // U[c][m] = sum_k ea[c][k]*G[k][m]; 4 k-chunks of 32
        const int m  = tid & 127;
        const int kq = tid >> 7;
        float u0 = 0.0f, u1 = 0.0f, u2 = 0.0f;
        if (m < 100) {
            const int kb = kq * 32;
            const int ke = (kq == 3) ? KNB : kb + 32;
            const float* gp = sm + OFF_X + m;
            const float* ep = sm + OFF_EA + bb * 384;
            #pragma unroll 4
            for (int kk = kb; kk < ke; kk++) {
                float gv = gp[kk * GSTR];
                u0 = fmaf(ep[kk],       gv, u0);
                u1 = fmaf(ep[128 + kk], gv, u1);
                u2 = fmaf(ep[256 + kk], gv, u2);
            }
            sm[OFF_UP + kq * 312 + m]       = u0;
            sm[OFF_UP + kq * 312 + 104 + m] = u1;
            sm[OFF_UP + kq * 312 + 208 + m] = u2;
        }
        __syncthreads();
        float us0 = 0.0f, us1 = 0.0f, us2 = 0.0f;
        if (tid < 100) {
            #pragma unroll
            for (int qq = 0; qq < 4; qq++) {
                us0 += sm[OFF_UP + qq * 312 + tid];
                us1 += sm[OFF_UP + qq * 312 + 104 + tid];
                us2 += sm[OFF_UP + qq * 312 + 208 + tid];
            }
            sm[OFF_US + tid]       = us0;
            sm[OFF_US + 104 + tid] = us1;
            sm[OFF_US + 208 + tid] = us2;
        }
        __syncthreads();
        if (tid < 100) {
            float4 r;
            r.x = us0 * sm[OFF_US + 0] + us1 * sm[OFF_US + 104 + 0] + us2 * sm[OFF_US + 208 + 0];
            r.y = us0 * sm[OFF_US + 1] + us1 * sm[OFF_US + 104 + 1] + us2 * sm[OFF_US + 208 + 1];
            r.z = us0 * sm[OFF_US + 2] + us1 * sm[OFF_US + 104 + 2] + us2 * sm[OFF_US + 208 + 2];
            r.w = us0 * sm[OFF_US + 3] + us1 * sm[OFF_US + 104 + 3] + us2 * sm[OFF_US + 208 + 3];
            *(float4*)(out + ((size_t)(b0i + bb) * NATOM + n) * 400 + tid * 4) = r;
        }
        __syncthreads();   // G reads done before next batch's stores
    }
}

__global__ void __launch_bounds__(THREADS, 1)
feat_kernel(const float* __restrict__ coords, const int* __restrict__ types,
            const float* __restrict__ W0g, const float* __restrict__ B0g,
            const float* __restrict__ W1g, const float* __restrict__ B1g,
            const float* __restrict__ W2g, const float* __restrict__ B2g,
            float* __restrict__ out)
{
    const int n    = blockIdx.x;
    const int tid  = threadIdx.x;
    const int warp = tid >> 5;
    const int lane = tid & 31;
    const int pw   = warp & 3;
    const int qt   = warp >> 2;
    int* smi = (int*)sm;

    const int eb = types[n] * 4;

    for (int i = OFF_W0 + tid; i < OFF_CS; i += THREADS) sm[i] = 0.0f;
    if (tid < 128) smi[OFF_TY + tid] = types[tid];
    __syncthreads();

    for (int i = tid; i < 100; i += THREADS) {
        int o = i % 25, e = i / 25;
        sm[OFF_W0 + e * 40 + o] = W0g[(eb + e) * 25 + o];
        sm[OFF_B0 + e * 40 + o] = B0g[(eb + e) * 25 + o];
    }
    for (int idx = tid; idx < 4 * 50 * 25; idx += THREADS) {
        int i = idx % 25, o = (idx / 25) % 50, e = idx / 1250;
        int pos = (o < 13) ? o : (o < 26) ? o + 3 : (o < 38) ? o + 6 : o + 10;
        sm[OFF_W1 + e * E1STR + i * 64 + pos] = W1g[(eb + e) * 1250 + o * 25 + i];
    }
    for (int idx = tid; idx < 200; idx += THREADS) {
        int o = idx % 50, e = idx / 50;
        int pos = (o < 13) ? o : (o < 26) ? o + 3 : (o < 38) ? o + 6 : o + 10;
        sm[OFF_B1 + e * 72 + pos] = B1g[(eb + e) * 50 + o];
    }
    for (int idx = tid; idx < 4 * 100 * 50; idx += THREADS) {
        int i = idx % 50, m = (idx / 50) % 100, e = idx / 5000;
        int pos = m + 3 * (m / 25);
        sm[OFF_W2 + e * E2STR + i * 112 + pos] = W2g[(eb + e) * 5000 + m * 50 + i];
    }
    for (int idx = tid; idx < 400; idx += THREADS) {
        int m = idx % 100, e = idx / 100;
        int pos = m + 3 * (m / 25);
        sm[OFF_B2 + e * 136 + pos] = B2g[(eb + e) * 100 + m];
    }

    if (tid < 4) {
        int c = 0;
        for (int j2 = 0; j2 < 128; j2++)
            if (j2 != n && smi[OFF_TY + j2] == tid) c++;
        smi[OFF_CNT + tid] = c;
    }
    __syncthreads();
    if (tid == 0) {
        int s = 0;
        #pragma unroll
        for (int e = 0; e < 4; e++) { smi[OFF_ST + e] = s; s += smi[OFF_CNT + e]; }
        smi[OFF_ST + 4] = s;
    }
    __syncthreads();
    if (tid < 128 && tid != n) {
        int t = smi[OFF_TY + tid];
        int r = 0;
        for (int j2 = 0; j2 < tid; j2++)
            if (j2 != n && smi[OFF_TY + j2] == t) r++;
        smi[OFF_SIDX + smi[OFF_ST + t] + r] = tid;
    }
    __syncthreads();

    const int  slot   = (pw << 5) + lane;
    const bool active = slot < KNB;
    const int  j = active ? smi[OFF_SIDX + slot] : n;
    const int  e = active ? smi[OFF_TY + j] : 0;

    const float* w0e = sm + OFF_W0 + e * 40;
    const float* b0e = sm + OFF_B0 + e * 40;
    const float* w1q = sm + OFF_W1 + e * E1STR + 16 * qt;
    const float* b1q = sm + OFF_B1 + e * 72 + 16 * qt;
    const float* w2q = sm + OFF_W2 + e * E2STR + 28 * qt;
    const float* b2q = sm + OFF_B2 + e * 136 + 28 * qt;
    const int sz1    = (qt < 2) ? 13 : 12;
    const int tbase1 = (qt < 2) ? 13 * qt : 12 * qt + 2;
    const int barid  = 1 + pw;
    const int bbase  = blockIdx.y * BT;

    tile_body<3>(coords, out, n, tid, qt, slot, active, j,
                 w0e, b0e, w1q, b1q, w2q, b2q, tbase1, sz1, barid, bbase);
    tile_body<3>(coords, out, n, tid, qt, slot, active, j,
                 w0e, b0e, w1q, b1q, w2q, b2q, tbase1, sz1, barid, bbase + 3);
    tile_body<2>(coords, out, n, tid, qt, slot, active, j,
                 w0e, b0e, w1q, b1q, w2q, b2q, tbase1, sz1, barid, bbase + 6);
}

extern "C" void kernel_launch(void* const* d_in, const int* in_sizes, int n_in,
                              void* d_out, int out_size)
{
    (void)in_sizes; (void)n_in; (void)out_size;
    const float* coords = (const float*)d_in[0];
    const int*   types  = (const int*)d_in[1];
    const float* W0g = (const float*)d_in[2];
    const float* B0g = (const float*)d_in[3];
    const float* W1g = (const float*)d_in[4];
    const float* B1g = (const float*)d_in[5];
    const float* W2g = (const float*)d_in[6];
    const float* B2g = (const float*)d_in[7];
    float* out = (float*)d_out;

    cudaFuncSetAttribute(feat_kernel, cudaFuncAttributeMaxDynamicSharedMemorySize, SMEM_BYTES);

    dim3 grid(NATOM, NBATCH / BT);   // (128, 8)
    feat_kernel<<<grid, THREADS, SMEM_BYTES>>>(coords, types,
                                               W0g, B0g, W1g, B1g, W2g, B2g, out);
}